// round 1
// baseline (speedup 1.0000x reference)
#include <cuda_runtime.h>
#include <cstdint>

#define NUM_E 1024
#define EDIM  256
#define BATCH 32
#define HW    1024          // 32*32
#define NROWS (BATCH*HW)    // 32768

// Scratch (no allocations allowed)
__device__ float g_cbnorm[NUM_E];          // ||e_k||^2
__device__ float g_cbT[EDIM * NUM_E];      // codebook transposed [c][k]
__device__ int   g_argmin[NROWS];

// ---------- packed f32x2 helpers (Blackwell) ----------
__device__ __forceinline__ unsigned long long pack2(float x, float y) {
    unsigned long long r;
    asm("mov.b64 %0, {%1, %2};" : "=l"(r) : "f"(x), "f"(y));
    return r;
}
__device__ __forceinline__ unsigned long long fma2(unsigned long long a,
                                                   unsigned long long b,
                                                   unsigned long long c) {
    unsigned long long d;
    asm("fma.rn.f32x2 %0, %1, %2, %3;" : "=l"(d) : "l"(a), "l"(b), "l"(c));
    return d;
}
__device__ __forceinline__ float lo32(unsigned long long u) {
    return __uint_as_float((unsigned)(u & 0xffffffffull));
}
__device__ __forceinline__ float hi32(unsigned long long u) {
    return __uint_as_float((unsigned)(u >> 32));
}

// ---------- prep: codebook norms + transpose ----------
__global__ __launch_bounds__(256) void prep_kernel(const float* __restrict__ cb) {
    int k = blockIdx.x;       // 0..1023
    int t = threadIdx.x;      // 0..255
    float v = cb[(size_t)k * EDIM + t];
    g_cbT[(size_t)t * NUM_E + k] = v;
    float sq = v * v;
    // warp reduce
    #pragma unroll
    for (int off = 16; off; off >>= 1)
        sq += __shfl_down_sync(0xffffffffu, sq, off);
    __shared__ float ws[8];
    int lane = t & 31, wid = t >> 5;
    if (lane == 0) ws[wid] = sq;
    __syncthreads();
    if (t == 0) {
        float s = 0.f;
        #pragma unroll
        for (int i = 0; i < 8; i++) s += ws[i];
        g_cbnorm[k] = s;
    }
}

// ---------- main: fused GEMM (f32x2) + argmin ----------
// Grid: NROWS/64 = 512 blocks, 256 threads.
// Block tile: M=64 rows x Ktile=128 codewords, C chunked by 8.
__global__ __launch_bounds__(256) void vq_argmin_kernel(const float* __restrict__ z,
                                                        const float* __restrict__ cb) {
    __shared__ __align__(16) float As[8][64];
    __shared__ __align__(16) float Bs[8][132];   // stride 132 -> conflict-free stores, 16B-aligned rows

    const int t  = threadIdx.x;
    const int tx = t & 15;        // col group: cols tx*8 .. tx*8+7
    const int ty = t >> 4;        // row group: rows ty*4 .. ty*4+3
    const int n0 = blockIdx.x * 64;
    const int b  = n0 >> 10;
    const int hw0 = n0 & 1023;
    const float* zb = z + (size_t)b * (EDIM * HW) + hw0;   // zb[c*1024 + i]

    float minv[4]; int mink[4];
    #pragma unroll
    for (int i = 0; i < 4; i++) { minv[i] = 3.4e38f; mink[i] = 0; }

    for (int k0 = 0; k0 < NUM_E; k0 += 128) {
        unsigned long long acc[4][4];
        #pragma unroll
        for (int i = 0; i < 4; i++)
            #pragma unroll
            for (int p = 0; p < 4; p++) acc[i][p] = 0ull;

        float cbn[8];
        #pragma unroll
        for (int j = 0; j < 8; j++) cbn[j] = __ldg(&g_cbnorm[k0 + tx * 8 + j]);

        for (int c0 = 0; c0 < EDIM; c0 += 8) {
            __syncthreads();
            // A tile: 8 c-rows x 64 cols (coalesced, 2 elems/thread)
            {
                int e0 = t;
                As[e0 >> 6][e0 & 63] = zb[(size_t)(c0 + (e0 >> 6)) * HW + (e0 & 63)];
                int e1 = t + 256;
                As[e1 >> 6][e1 & 63] = zb[(size_t)(c0 + (e1 >> 6)) * HW + (e1 & 63)];
            }
            // B tile: 128 k x 8 c (float4 per thread), stored transposed Bs[c][k]
            {
                int kk = t >> 1;
                int coff = (t & 1) * 4;
                float4 v = *(const float4*)&cb[(size_t)(k0 + kk) * EDIM + c0 + coff];
                Bs[coff + 0][kk] = v.x;
                Bs[coff + 1][kk] = v.y;
                Bs[coff + 2][kk] = v.z;
                Bs[coff + 3][kk] = v.w;
            }
            __syncthreads();
            #pragma unroll
            for (int cc = 0; cc < 8; cc++) {
                float4 a4 = *(const float4*)&As[cc][ty * 4];
                ulonglong2 b01 = *(const ulonglong2*)&Bs[cc][tx * 8];
                ulonglong2 b23 = *(const ulonglong2*)&Bs[cc][tx * 8 + 4];
                unsigned long long av0 = pack2(a4.x, a4.x);
                unsigned long long av1 = pack2(a4.y, a4.y);
                unsigned long long av2 = pack2(a4.z, a4.z);
                unsigned long long av3 = pack2(a4.w, a4.w);
                acc[0][0] = fma2(av0, b01.x, acc[0][0]);
                acc[0][1] = fma2(av0, b01.y, acc[0][1]);
                acc[0][2] = fma2(av0, b23.x, acc[0][2]);
                acc[0][3] = fma2(av0, b23.y, acc[0][3]);
                acc[1][0] = fma2(av1, b01.x, acc[1][0]);
                acc[1][1] = fma2(av1, b01.y, acc[1][1]);
                acc[1][2] = fma2(av1, b23.x, acc[1][2]);
                acc[1][3] = fma2(av1, b23.y, acc[1][3]);
                acc[2][0] = fma2(av2, b01.x, acc[2][0]);
                acc[2][1] = fma2(av2, b01.y, acc[2][1]);
                acc[2][2] = fma2(av2, b23.x, acc[2][2]);
                acc[2][3] = fma2(av2, b23.y, acc[2][3]);
                acc[3][0] = fma2(av3, b01.x, acc[3][0]);
                acc[3][1] = fma2(av3, b01.y, acc[3][1]);
                acc[3][2] = fma2(av3, b23.x, acc[3][2]);
                acc[3][3] = fma2(av3, b23.y, acc[3][3]);
            }
        }

        // epilogue: d = ||e||^2 - 2*s ; local argmin over 8 cols (ascending k, strict <)
        #pragma unroll
        for (int i = 0; i < 4; i++) {
            float v = 3.4e38f; int vk = 0;
            #pragma unroll
            for (int p = 0; p < 4; p++) {
                float s0 = lo32(acc[i][p]);
                float s1 = hi32(acc[i][p]);
                float d0 = cbn[2 * p]     - 2.0f * s0;
                float d1 = cbn[2 * p + 1] - 2.0f * s1;
                int kbase = k0 + tx * 8 + 2 * p;
                if (d0 < v) { v = d0; vk = kbase; }
                if (d1 < v) { v = d1; vk = kbase + 1; }
            }
            // reduce across the 16 tx lanes (lower lane = smaller k wins ties)
            #pragma unroll
            for (int off = 8; off; off >>= 1) {
                float ov = __shfl_down_sync(0xffffffffu, v, off, 16);
                int   oi = __shfl_down_sync(0xffffffffu, vk, off, 16);
                if (ov < v) { v = ov; vk = oi; }
            }
            if (tx == 0) {
                if (v < minv[i]) { minv[i] = v; mink[i] = vk; }
            }
        }
    }

    if (tx == 0) {
        #pragma unroll
        for (int i = 0; i < 4; i++)
            g_argmin[n0 + ty * 4 + i] = mink[i];
    }
}

// ---------- outputs ----------
// one-hot rows: block per row, 256 threads x float4
__global__ __launch_bounds__(256) void onehot_kernel(float* __restrict__ out) {
    int r = blockIdx.x;
    int t = threadIdx.x;
    int idx = g_argmin[r];
    int c0 = t * 4;
    float4 v;
    v.x = (idx == c0 + 0) ? 1.0f : 0.0f;
    v.y = (idx == c0 + 1) ? 1.0f : 0.0f;
    v.z = (idx == c0 + 2) ? 1.0f : 0.0f;
    v.w = (idx == c0 + 3) ? 1.0f : 0.0f;
    *(float4*)&out[(size_t)r * NUM_E + c0] = v;
}

// z_quantized[b,c,hw] = cbT[c][argmin[b*1024+hw]]  (linear index == b*262144 + c*1024 + hw)
__global__ __launch_bounds__(256) void quant_kernel(float* __restrict__ outq) {
    int i = blockIdx.x * blockDim.x + threadIdx.x;   // float4 id, total 2097152
    int flat = i * 4;
    int hw = flat & 1023;
    int c  = (flat >> 10) & 255;
    int b  = flat >> 18;
    int4 idx4 = *(const int4*)&g_argmin[b * 1024 + hw];
    const float* row = &g_cbT[(size_t)c * NUM_E];
    float4 v;
    v.x = row[idx4.x];
    v.y = row[idx4.y];
    v.z = row[idx4.z];
    v.w = row[idx4.w];
    *(float4*)&outq[flat] = v;
}

extern "C" void kernel_launch(void* const* d_in, const int* in_sizes, int n_in,
                              void* d_out, int out_size) {
    const float* z  = (const float*)d_in[0];
    const float* cb = (const float*)d_in[1];
    float* out_onehot = (float*)d_out;
    float* out_q      = (float*)d_out + (size_t)NROWS * NUM_E;

    prep_kernel<<<NUM_E, 256>>>(cb);
    vq_argmin_kernel<<<NROWS / 64, 256>>>(z, cb);
    onehot_kernel<<<NROWS, 256>>>(out_onehot);
    quant_kernel<<<(NROWS * EDIM) / 4 / 256, 256>>>(out_q);
}